// round 11
// baseline (speedup 1.0000x reference)
#include <cuda_runtime.h>
#include <cuda_fp16.h>
#include <math.h>
#include <stdint.h>

#define B_TOK 8192
#define DIN   1024
#define DH    512
#define NE    8
#define DOUT  1024

// ======================= scratch (__device__ globals) =======================
__device__ float g_gate[B_TOK * DH];
__device__ float g_hpre[(size_t)NE * B_TOK * DOUT];
__device__ int   g_tok[NE * B_TOK];
__device__ int   g_cnt[NE];
__device__ int   g_slot[B_TOK * 2];
__device__ float g_wgt[B_TOK * 2];
// fp16 hi/lo split operands
__device__ uint4 g_xhi[(size_t)B_TOK * DIN / 8];                  // x hi [8192][1024] f16
__device__ uint4 g_xlo[(size_t)B_TOK * DIN / 8];                  // x lo (gate only)
__device__ __align__(16) __half g_w1hi[(size_t)DH * DIN];         // W1^T [n][k]
__device__ __align__(16) __half g_w1lo[(size_t)DH * DIN];
__device__ __align__(16) __half g_wehi[(size_t)NE * DOUT * DIN];  // We^T [e][n][k] (hi only)

__device__ __forceinline__ float gelu_exact(float v) {
    return 0.5f * v * (1.0f + erff(v * 0.70710678118654752f));
}
__device__ __forceinline__ uint32_t smem_u32(const void* p) {
    uint32_t a;
    asm("{ .reg .u64 t; cvta.to.shared.u64 t, %1; cvt.u32.u64 %0, t; }" : "=r"(a) : "l"(p));
    return a;
}
__device__ __forceinline__ void cp16(uint32_t s, const void* g) {
    asm volatile("cp.async.cg.shared.global [%0], [%1], 16;" :: "r"(s), "l"(g) : "memory");
}
__device__ __forceinline__ void cp_commit() { asm volatile("cp.async.commit_group;" ::: "memory"); }
__device__ __forceinline__ void cp_wait1()  { asm volatile("cp.async.wait_group 1;" ::: "memory"); }
__device__ __forceinline__ void cp_wait0()  { asm volatile("cp.async.wait_group 0;" ::: "memory"); }
__device__ __forceinline__ void ldm4(uint32_t* r, uint32_t a) {
    asm volatile("ldmatrix.sync.aligned.m8n8.x4.shared.b16 {%0,%1,%2,%3}, [%4];"
                 : "=r"(r[0]), "=r"(r[1]), "=r"(r[2]), "=r"(r[3]) : "r"(a));
}
__device__ __forceinline__ void mma16816(float* d, const uint32_t* a, const uint32_t* b) {
    asm volatile("mma.sync.aligned.m16n8k16.row.col.f32.f16.f16.f32 "
                 "{%0,%1,%2,%3}, {%4,%5,%6,%7}, {%8,%9}, {%0,%1,%2,%3};"
                 : "+f"(d[0]), "+f"(d[1]), "+f"(d[2]), "+f"(d[3])
                 : "r"(a[0]), "r"(a[1]), "r"(a[2]), "r"(a[3]), "r"(b[0]), "r"(b[1]));
}

// ======================= convert x -> fp16 hi/lo (+ zero counters) =======================
__global__ __launch_bounds__(256) void convert_x_kernel(const float* __restrict__ x) {
    if (blockIdx.x == 0 && threadIdx.x < NE) g_cnt[threadIdx.x] = 0;
    size_t i = ((size_t)blockIdx.x * 256 + threadIdx.x) * 4;
    float4 v = *(const float4*)(x + i);
    float vv[4] = {v.x, v.y, v.z, v.w};
    uint32_t hb[4], lb[4];
#pragma unroll
    for (int j = 0; j < 4; ++j) {
        __half h = __float2half_rn(vv[j]);
        __half l = __float2half_rn(vv[j] - __half2float(h));
        hb[j] = (uint32_t)__half_as_ushort(h);
        lb[j] = (uint32_t)__half_as_ushort(l);
    }
    ((uint2*)g_xhi)[i / 4] = make_uint2(hb[0] | (hb[1] << 16), hb[2] | (hb[3] << 16));
    ((uint2*)g_xlo)[i / 4] = make_uint2(lb[0] | (lb[1] << 16), lb[2] | (lb[3] << 16));
}

// ======================= W1[k][n] fp32 -> W1^T[n][k] fp16 hi/lo =======================
__global__ __launch_bounds__(256) void convert_w1_kernel(const float* __restrict__ W1) {
    __shared__ float t[32][33];
    const int n0 = blockIdx.x * 32, k0 = blockIdx.y * 32;
    const int tx = threadIdx.x & 31, ty = threadIdx.x >> 5;
#pragma unroll
    for (int s = 0; s < 32; s += 8)
        t[ty + s][tx] = W1[((size_t)(k0 + ty + s)) * DH + n0 + tx];
    __syncthreads();
#pragma unroll
    for (int s = 0; s < 32; s += 8) {
        float v = t[tx][ty + s];
        __half h = __float2half_rn(v);
        __half l = __float2half_rn(v - __half2float(h));
        size_t o = ((size_t)(n0 + ty + s)) * DIN + k0 + tx;
        g_w1hi[o] = h;
        g_w1lo[o] = l;
    }
}

// ======================= We[e][k][n] fp32 -> We^T[e][n][k] fp16 (hi only) =======================
__global__ __launch_bounds__(256) void convert_we_kernel(const float* __restrict__ We) {
    __shared__ float t[32][33];
    const int e = blockIdx.z;
    const int n0 = blockIdx.x * 32, k0 = blockIdx.y * 32;
    const int tx = threadIdx.x & 31, ty = threadIdx.x >> 5;
#pragma unroll
    for (int s = 0; s < 32; s += 8)
        t[ty + s][tx] = We[((size_t)e * DIN + k0 + ty + s) * DOUT + n0 + tx];
    __syncthreads();
#pragma unroll
    for (int s = 0; s < 32; s += 8) {
        float v = t[tx][ty + s];
        size_t o = ((size_t)e * DOUT + n0 + ty + s) * DIN + k0 + tx;
        g_wehi[o] = __float2half_rn(v);
    }
}

// ======================= gate geometry (K-chunk 32) =======================
#define TPAD        80
#define TILE_B      10240
#define GATE_STAGE  40960
#define GATE_SMEM   81920

// ======================= gate1: x @ W1 via fp16 3-term mma + GELU =======================
__global__ __launch_bounds__(256, 2) void gate1_mma_kernel(const float* __restrict__ b1) {
    extern __shared__ char smem[];
    const int m0 = blockIdx.y * 128;
    const int n0 = blockIdx.x * 128;
    const int tid = threadIdx.x;
    const uint32_t sb = smem_u32(smem);

    const int lrow = tid >> 1, half_ = tid & 1;
    const uint4* srcAh = g_xhi + (size_t)(m0 + lrow) * 128 + half_ * 2;
    const uint4* srcAl = g_xlo + (size_t)(m0 + lrow) * 128 + half_ * 2;
    const uint4* srcBh = (const uint4*)g_w1hi + (size_t)(n0 + lrow) * 128 + half_ * 2;
    const uint4* srcBl = (const uint4*)g_w1lo + (size_t)(n0 + lrow) * 128 + half_ * 2;
    const uint32_t dstoff = (uint32_t)(lrow * TPAD + half_ * 32);

    const int lane = tid & 31, wid = tid >> 5;
    const int wm = wid & 1, wn = wid >> 1;
    const uint32_t a_off = (uint32_t)((wm * 64 + (lane & 15)) * TPAD + (lane >> 4) * 16);
    const uint32_t b_off = (uint32_t)((wn * 32 + (lane & 7) + ((lane >> 4) << 3)) * TPAD +
                                      ((lane >> 3) & 1) * 16);

    float acc[4][4][4];
#pragma unroll
    for (int i = 0; i < 4; ++i)
#pragma unroll
        for (int j = 0; j < 4; ++j)
#pragma unroll
            for (int c = 0; c < 4; ++c) acc[i][j][c] = 0.0f;

    {
        const uint32_t base = sb;
#pragma unroll
        for (int c = 0; c < 2; ++c) {
            cp16(base + 0 * TILE_B + dstoff + c * 16, srcAh + c);
            cp16(base + 1 * TILE_B + dstoff + c * 16, srcAl + c);
            cp16(base + 2 * TILE_B + dstoff + c * 16, srcBh + c);
            cp16(base + 3 * TILE_B + dstoff + c * 16, srcBl + c);
        }
        cp_commit();
    }

    for (int kb = 0; kb < 32; ++kb) {
        const int cur = kb & 1;
        if (kb + 1 < 32) {
            const uint32_t base = sb + (1 - cur) * GATE_STAGE;
            const int co = (kb + 1) * 4;
#pragma unroll
            for (int c = 0; c < 2; ++c) {
                cp16(base + 0 * TILE_B + dstoff + c * 16, srcAh + co + c);
                cp16(base + 1 * TILE_B + dstoff + c * 16, srcAl + co + c);
                cp16(base + 2 * TILE_B + dstoff + c * 16, srcBh + co + c);
                cp16(base + 3 * TILE_B + dstoff + c * 16, srcBl + co + c);
            }
            cp_commit();
            cp_wait1();
        } else {
            cp_wait0();
        }
        __syncthreads();

        const uint32_t sAh = sb + cur * GATE_STAGE;
        const uint32_t sAl = sAh + TILE_B;
        const uint32_t sBh = sAh + 2 * TILE_B;
        const uint32_t sBl = sAh + 3 * TILE_B;
#pragma unroll
        for (int k16 = 0; k16 < 2; ++k16) {
            const uint32_t kadd = k16 * 32;
            uint32_t ah[4][4], al[4][4], bh[2][4], bl[2][4];
#pragma unroll
            for (int mt = 0; mt < 4; ++mt) {
                ldm4(ah[mt], sAh + a_off + mt * (16 * TPAD) + kadd);
                ldm4(al[mt], sAl + a_off + mt * (16 * TPAD) + kadd);
            }
#pragma unroll
            for (int g = 0; g < 2; ++g) {
                ldm4(bh[g], sBh + b_off + g * (16 * TPAD) + kadd);
                ldm4(bl[g], sBl + b_off + g * (16 * TPAD) + kadd);
            }
#pragma unroll
            for (int mt = 0; mt < 4; ++mt)
#pragma unroll
                for (int nt = 0; nt < 4; ++nt) {
                    const uint32_t* ph = &bh[nt >> 1][(nt & 1) * 2];
                    const uint32_t* pl = &bl[nt >> 1][(nt & 1) * 2];
                    mma16816(acc[mt][nt], ah[mt], ph);
                    mma16816(acc[mt][nt], al[mt], ph);
                    mma16816(acc[mt][nt], ah[mt], pl);
                }
        }
        __syncthreads();
    }

    // epilogue: bias + exact GELU -> g_gate (fp32)
#pragma unroll
    for (int mt = 0; mt < 4; ++mt) {
        const int rbase = m0 + wm * 64 + mt * 16 + (lane >> 2);
#pragma unroll
        for (int h = 0; h < 2; ++h) {
            const int gr = rbase + h * 8;
            float* gp = g_gate + (size_t)gr * DH + n0;
#pragma unroll
            for (int nt = 0; nt < 4; ++nt) {
                const int col = wn * 32 + nt * 8 + (lane & 3) * 2;
                float2 v;
                v.x = gelu_exact(acc[mt][nt][h * 2 + 0] + b1[n0 + col]);
                v.y = gelu_exact(acc[mt][nt][h * 2 + 1] + b1[n0 + col + 1]);
                *(float2*)(gp + col) = v;
            }
        }
    }
}

// ======================= routing (fp32 exact) =======================
__global__ __launch_bounds__(256) void routing_kernel(const float* __restrict__ W2,
                                                      const float* __restrict__ b2) {
    __shared__ float sW[NE * DH];
    const int tid = threadIdx.x;
    for (int idx = tid; idx < NE * DH; idx += 256) {
        int k = idx >> 3, j = idx & 7;
        sW[j * DH + k] = W2[idx];
    }
    __syncthreads();

    const int warp = tid >> 5, lane = tid & 31;
    const int b = blockIdx.x * 8 + warp;
    const float* gr = g_gate + (size_t)b * DH;

    float acc[NE];
#pragma unroll
    for (int j = 0; j < NE; ++j) acc[j] = 0.0f;
    for (int k = lane; k < DH; k += 32) {
        float gv = gr[k];
#pragma unroll
        for (int j = 0; j < NE; ++j) acc[j] += gv * sW[j * DH + k];
    }
#pragma unroll
    for (int off = 16; off; off >>= 1)
#pragma unroll
        for (int j = 0; j < NE; ++j)
            acc[j] += __shfl_down_sync(0xffffffffu, acc[j], off);

    if (lane == 0) {
        float s[NE];
#pragma unroll
        for (int j = 0; j < NE; ++j) s[j] = acc[j] + b2[j];
        int i0 = 0; float s0v = s[0];
#pragma unroll
        for (int j = 1; j < NE; ++j) if (s[j] > s0v) { s0v = s[j]; i0 = j; }
        int i1 = -1; float s1v = -3.4e38f;
#pragma unroll
        for (int j = 0; j < NE; ++j) if (j != i0 && s[j] > s1v) { s1v = s[j]; i1 = j; }
        float ed = expf(s1v - s0v);
        float denom = 1.0f + ed;
        float w0 = 1.0f / denom, w1 = ed / denom;

        int p0 = atomicAdd(&g_cnt[i0], 1);
        int p1 = atomicAdd(&g_cnt[i1], 1);
        g_tok[i0 * B_TOK + p0] = b;
        g_tok[i1 * B_TOK + p1] = b;
        g_slot[2 * b]     = i0 * B_TOK + p0;
        g_slot[2 * b + 1] = i1 * B_TOK + p1;
        g_wgt[2 * b]      = w0;
        g_wgt[2 * b + 1]  = w1;
    }
}

// ======================= expert GEMM: single-term Ah*Bh, K-chunk 64 =======================
// Tiles: 128 rows x 64 f16, rows padded to 144 B (conflict-free: banks 4r+c).
// Stage = Ah|Bh (2 tiles). Double-buffered.
#define ETPAD     144
#define ETILE_B   18432          // 128*144
#define EXP_STAGE 36864          // 2 tiles
#define EXP_SMEM  73728          // 2 stages

__global__ __launch_bounds__(256, 2) void expert_mma_kernel(const float* __restrict__ be) {
    extern __shared__ char smem[];
    __shared__ int ts[128];
    const int e   = blockIdx.z;
    const int cnt = g_cnt[e];
    const int m0  = blockIdx.y * 128;
    if (m0 >= cnt) return;
    const int n0  = blockIdx.x * 128;
    const int tid = threadIdx.x;
    const uint32_t sb = smem_u32(smem);

    if (tid < 128) {
        int r = m0 + tid;
        ts[tid] = (r < cnt) ? g_tok[e * B_TOK + r] : g_tok[e * B_TOK];
    }
    __syncthreads();

    // each thread loads half a row (64 B = 4 x 16B) per tile per k-chunk
    const int lrow = tid >> 1, half_ = tid & 1;
    const int mytok = ts[lrow];
    const uint4* srcA = g_xhi + (size_t)mytok * 128 + half_ * 4;
    const uint4* srcB = (const uint4*)g_wehi + (size_t)(e * DOUT + n0 + lrow) * 128 + half_ * 4;
    const uint32_t dstoff = (uint32_t)(lrow * ETPAD + half_ * 64);

    const int lane = tid & 31, wid = tid >> 5;
    const int wm = wid & 1, wn = wid >> 1;
    const uint32_t a_off = (uint32_t)((wm * 64 + (lane & 15)) * ETPAD + (lane >> 4) * 16);
    const uint32_t b_off = (uint32_t)((wn * 32 + (lane & 7) + ((lane >> 4) << 3)) * ETPAD +
                                      ((lane >> 3) & 1) * 16);

    float acc[4][4][4];
#pragma unroll
    for (int i = 0; i < 4; ++i)
#pragma unroll
        for (int j = 0; j < 4; ++j)
#pragma unroll
            for (int c = 0; c < 4; ++c) acc[i][j][c] = 0.0f;

    {
        const uint32_t base = sb;
#pragma unroll
        for (int c = 0; c < 4; ++c) {
            cp16(base + 0 * ETILE_B + dstoff + c * 16, srcA + c);
            cp16(base + 1 * ETILE_B + dstoff + c * 16, srcB + c);
        }
        cp_commit();
    }

    for (int kb = 0; kb < 16; ++kb) {       // 16 chunks of K=64
        const int cur = kb & 1;
        if (kb + 1 < 16) {
            const uint32_t base = sb + (1 - cur) * EXP_STAGE;
            const int co = (kb + 1) * 8;
#pragma unroll
            for (int c = 0; c < 4; ++c) {
                cp16(base + 0 * ETILE_B + dstoff + c * 16, srcA + co + c);
                cp16(base + 1 * ETILE_B + dstoff + c * 16, srcB + co + c);
            }
            cp_commit();
            cp_wait1();
        } else {
            cp_wait0();
        }
        __syncthreads();

        const uint32_t sA = sb + cur * EXP_STAGE;
        const uint32_t sB = sA + ETILE_B;
#pragma unroll
        for (int k16 = 0; k16 < 4; ++k16) {
            const uint32_t kadd = k16 * 32;
            uint32_t ah[4][4], bh[2][4];
#pragma unroll
            for (int mt = 0; mt < 4; ++mt)
                ldm4(ah[mt], sA + a_off + mt * (16 * ETPAD) + kadd);
#pragma unroll
            for (int g = 0; g < 2; ++g)
                ldm4(bh[g], sB + b_off + g * (16 * ETPAD) + kadd);
#pragma unroll
            for (int mt = 0; mt < 4; ++mt)
#pragma unroll
                for (int nt = 0; nt < 4; ++nt) {
                    const uint32_t* ph = &bh[nt >> 1][(nt & 1) * 2];
                    mma16816(acc[mt][nt], ah[mt], ph);
                }
        }
        __syncthreads();
    }

    // epilogue: bias + predicated store
    const float* bb = be + e * DOUT + n0;
#pragma unroll
    for (int mt = 0; mt < 4; ++mt) {
        const int rbase = wm * 64 + mt * 16 + (lane >> 2);
#pragma unroll
        for (int h = 0; h < 2; ++h) {
            const int gr = m0 + rbase + h * 8;
            if (gr < cnt) {
                float* hp = g_hpre + ((size_t)e * B_TOK + gr) * DOUT + n0;
#pragma unroll
                for (int nt = 0; nt < 4; ++nt) {
                    const int col = wn * 32 + nt * 8 + (lane & 3) * 2;
                    float2 v;
                    v.x = acc[mt][nt][h * 2 + 0] + bb[col];
                    v.y = acc[mt][nt][h * 2 + 1] + bb[col + 1];
                    *(float2*)(hp + col) = v;
                }
            }
        }
    }
}

// ======================= LN + GELU + weighted combine =======================
__global__ __launch_bounds__(256) void combine_kernel(const float* __restrict__ ln_g,
                                                      const float* __restrict__ ln_b,
                                                      float* __restrict__ out) {
    const int b = blockIdx.x, tid = threadIdx.x;
    const int s0 = g_slot[2 * b], s1 = g_slot[2 * b + 1];
    const float w0 = g_wgt[2 * b], w1 = g_wgt[2 * b + 1];
    const int e0 = s0 >> 13, e1 = s1 >> 13;
    const float* r0 = g_hpre + (size_t)s0 * DOUT;
    const float* r1 = g_hpre + (size_t)s1 * DOUT;

    float v0[4], v1[4];
    float sum0 = 0.f, sq0 = 0.f, sum1 = 0.f, sq1 = 0.f;
#pragma unroll
    for (int i = 0; i < 4; ++i) {
        const int o = tid + i * 256;
        v0[i] = r0[o]; v1[i] = r1[o];
        sum0 += v0[i]; sq0 += v0[i] * v0[i];
        sum1 += v1[i]; sq1 += v1[i] * v1[i];
    }
    const int lane = tid & 31, wid = tid >> 5;
#pragma unroll
    for (int off = 16; off; off >>= 1) {
        sum0 += __shfl_down_sync(0xffffffffu, sum0, off);
        sq0  += __shfl_down_sync(0xffffffffu, sq0,  off);
        sum1 += __shfl_down_sync(0xffffffffu, sum1, off);
        sq1  += __shfl_down_sync(0xffffffffu, sq1,  off);
    }
    __shared__ float red[8][4];
    __shared__ float stats[4];
    if (lane == 0) { red[wid][0] = sum0; red[wid][1] = sq0; red[wid][2] = sum1; red[wid][3] = sq1; }
    __syncthreads();
    if (tid == 0) {
        float S0 = 0, Q0 = 0, S1 = 0, Q1 = 0;
#pragma unroll
        for (int w = 0; w < 8; ++w) { S0 += red[w][0]; Q0 += red[w][1]; S1 += red[w][2]; Q1 += red[w][3]; }
        const float inv = 1.0f / (float)DOUT;
        float mu0 = S0 * inv, mu1 = S1 * inv;
        float var0 = Q0 * inv - mu0 * mu0;
        float var1 = Q1 * inv - mu1 * mu1;
        stats[0] = mu0; stats[1] = rsqrtf(var0 + 1e-5f);
        stats[2] = mu1; stats[3] = rsqrtf(var1 + 1e-5f);
    }
    __syncthreads();
    const float mu0 = stats[0], rs0 = stats[1], mu1 = stats[2], rs1 = stats[3];
#pragma unroll
    for (int i = 0; i < 4; ++i) {
        const int o = tid + i * 256;
        const float h0 = (v0[i] - mu0) * rs0 * ln_g[e0 * DOUT + o] + ln_b[e0 * DOUT + o];
        const float h1 = (v1[i] - mu1) * rs1 * ln_g[e1 * DOUT + o] + ln_b[e1 * DOUT + o];
        out[(size_t)b * DOUT + o] = w0 * gelu_exact(h0) + w1 * gelu_exact(h1);
    }
}

// ======================= launch =======================
extern "C" void kernel_launch(void* const* d_in, const int* in_sizes, int n_in,
                              void* d_out, int out_size) {
    const float* x    = (const float*)d_in[0];
    const float* W1   = (const float*)d_in[1];
    const float* b1   = (const float*)d_in[2];
    const float* W2   = (const float*)d_in[3];
    const float* b2   = (const float*)d_in[4];
    const float* We   = (const float*)d_in[5];
    const float* be   = (const float*)d_in[6];
    const float* ln_g = (const float*)d_in[7];
    const float* ln_b = (const float*)d_in[8];
    float* out = (float*)d_out;

    cudaFuncSetAttribute(gate1_mma_kernel,  cudaFuncAttributeMaxDynamicSharedMemorySize, GATE_SMEM);
    cudaFuncSetAttribute(expert_mma_kernel, cudaFuncAttributeMaxDynamicSharedMemorySize, EXP_SMEM);

    convert_x_kernel<<<(B_TOK * DIN) / (256 * 4), 256>>>(x);
    convert_w1_kernel<<<dim3(DH / 32, DIN / 32), 256>>>(W1);
    convert_we_kernel<<<dim3(DOUT / 32, DIN / 32, NE), 256>>>(We);
    gate1_mma_kernel<<<dim3(DH / 128, B_TOK / 128), 256, GATE_SMEM>>>(b1);
    routing_kernel<<<B_TOK / 8, 256>>>(W2, b2);
    expert_mma_kernel<<<dim3(DOUT / 128, B_TOK / 128, NE), 256, EXP_SMEM>>>(be);
    combine_kernel<<<B_TOK, 256>>>(ln_g, ln_b, out);
}

// round 14
// speedup vs baseline: 1.3903x; 1.3903x over previous
#include <cuda_runtime.h>
#include <cuda_fp16.h>
#include <math.h>
#include <stdint.h>

#define B_TOK 8192
#define DIN   1024
#define DH    512
#define NE    8
#define DOUT  1024

// ======================= scratch (__device__ globals) =======================
__device__ float g_gate[B_TOK * DH];
__device__ float g_hpre[(size_t)NE * B_TOK * DOUT];
__device__ int   g_tok[NE * B_TOK];
__device__ int   g_cnt[NE];
__device__ int   g_slot[B_TOK * 2];
__device__ float g_wgt[B_TOK * 2];
// fp16 hi/lo split operands
__device__ uint4 g_xhi[(size_t)B_TOK * DIN / 8];                  // x hi [8192][1024] f16
__device__ uint4 g_xlo[(size_t)B_TOK * DIN / 8];                  // x lo (gate only)
__device__ __align__(16) __half g_w1hi[(size_t)DH * DIN];         // W1^T [n][k]
__device__ __align__(16) __half g_w1lo[(size_t)DH * DIN];
__device__ __align__(16) __half g_wehi[(size_t)NE * DOUT * DIN];  // We^T [e][n][k] (hi only)

__device__ __forceinline__ float gelu_exact(float v) {
    return 0.5f * v * (1.0f + erff(v * 0.70710678118654752f));
}
__device__ __forceinline__ uint32_t smem_u32(const void* p) {
    uint32_t a;
    asm("{ .reg .u64 t; cvta.to.shared.u64 t, %1; cvt.u32.u64 %0, t; }" : "=r"(a) : "l"(p));
    return a;
}
__device__ __forceinline__ void cp16(uint32_t s, const void* g) {
    asm volatile("cp.async.cg.shared.global [%0], [%1], 16;" :: "r"(s), "l"(g) : "memory");
}
__device__ __forceinline__ void cp_commit() { asm volatile("cp.async.commit_group;" ::: "memory"); }
__device__ __forceinline__ void cp_wait1()  { asm volatile("cp.async.wait_group 1;" ::: "memory"); }
__device__ __forceinline__ void cp_wait0()  { asm volatile("cp.async.wait_group 0;" ::: "memory"); }
__device__ __forceinline__ void ldm4(uint32_t* r, uint32_t a) {
    asm volatile("ldmatrix.sync.aligned.m8n8.x4.shared.b16 {%0,%1,%2,%3}, [%4];"
                 : "=r"(r[0]), "=r"(r[1]), "=r"(r[2]), "=r"(r[3]) : "r"(a));
}
__device__ __forceinline__ void mma16816(float* d, const uint32_t* a, const uint32_t* b) {
    asm volatile("mma.sync.aligned.m16n8k16.row.col.f32.f16.f16.f32 "
                 "{%0,%1,%2,%3}, {%4,%5,%6,%7}, {%8,%9}, {%0,%1,%2,%3};"
                 : "+f"(d[0]), "+f"(d[1]), "+f"(d[2]), "+f"(d[3])
                 : "r"(a[0]), "r"(a[1]), "r"(a[2]), "r"(a[3]), "r"(b[0]), "r"(b[1]));
}

// ======================= convert x -> fp16 hi/lo (+ zero counters) =======================
__global__ __launch_bounds__(256) void convert_x_kernel(const float* __restrict__ x) {
    if (blockIdx.x == 0 && threadIdx.x < NE) g_cnt[threadIdx.x] = 0;
    size_t i = ((size_t)blockIdx.x * 256 + threadIdx.x) * 4;
    float4 v = *(const float4*)(x + i);
    float vv[4] = {v.x, v.y, v.z, v.w};
    uint32_t hb[4], lb[4];
#pragma unroll
    for (int j = 0; j < 4; ++j) {
        __half h = __float2half_rn(vv[j]);
        __half l = __float2half_rn(vv[j] - __half2float(h));
        hb[j] = (uint32_t)__half_as_ushort(h);
        lb[j] = (uint32_t)__half_as_ushort(l);
    }
    ((uint2*)g_xhi)[i / 4] = make_uint2(hb[0] | (hb[1] << 16), hb[2] | (hb[3] << 16));
    ((uint2*)g_xlo)[i / 4] = make_uint2(lb[0] | (lb[1] << 16), lb[2] | (lb[3] << 16));
}

// ======================= W1[k][n] fp32 -> W1^T[n][k] fp16 hi/lo =======================
__global__ __launch_bounds__(256) void convert_w1_kernel(const float* __restrict__ W1) {
    __shared__ float t[32][33];
    const int n0 = blockIdx.x * 32, k0 = blockIdx.y * 32;
    const int tx = threadIdx.x & 31, ty = threadIdx.x >> 5;
#pragma unroll
    for (int s = 0; s < 32; s += 8)
        t[ty + s][tx] = W1[((size_t)(k0 + ty + s)) * DH + n0 + tx];
    __syncthreads();
#pragma unroll
    for (int s = 0; s < 32; s += 8) {
        float v = t[tx][ty + s];
        __half h = __float2half_rn(v);
        __half l = __float2half_rn(v - __half2float(h));
        size_t o = ((size_t)(n0 + ty + s)) * DIN + k0 + tx;
        g_w1hi[o] = h;
        g_w1lo[o] = l;
    }
}

// ======================= We[e][k][n] fp32 -> We^T[e][n][k] fp16 (hi only) =======================
__global__ __launch_bounds__(256) void convert_we_kernel(const float* __restrict__ We) {
    __shared__ float t[32][33];
    const int e = blockIdx.z;
    const int n0 = blockIdx.x * 32, k0 = blockIdx.y * 32;
    const int tx = threadIdx.x & 31, ty = threadIdx.x >> 5;
#pragma unroll
    for (int s = 0; s < 32; s += 8)
        t[ty + s][tx] = We[((size_t)e * DIN + k0 + ty + s) * DOUT + n0 + tx];
    __syncthreads();
#pragma unroll
    for (int s = 0; s < 32; s += 8) {
        float v = t[tx][ty + s];
        size_t o = ((size_t)e * DOUT + n0 + ty + s) * DIN + k0 + tx;
        g_wehi[o] = __float2half_rn(v);
    }
}

// ======================= gate geometry (K-chunk 32) =======================
#define TPAD        80
#define TILE_B      10240
#define GATE_STAGE  40960
#define GATE_SMEM   81920

// ======================= gate1: x @ W1 via fp16 3-term mma + GELU =======================
__global__ __launch_bounds__(256, 2) void gate1_mma_kernel(const float* __restrict__ b1) {
    extern __shared__ char smem[];
    const int m0 = blockIdx.y * 128;
    const int n0 = blockIdx.x * 128;
    const int tid = threadIdx.x;
    const uint32_t sb = smem_u32(smem);

    const int lrow = tid >> 1, half_ = tid & 1;
    const uint4* srcAh = g_xhi + (size_t)(m0 + lrow) * 128 + half_ * 2;
    const uint4* srcAl = g_xlo + (size_t)(m0 + lrow) * 128 + half_ * 2;
    const uint4* srcBh = (const uint4*)g_w1hi + (size_t)(n0 + lrow) * 128 + half_ * 2;
    const uint4* srcBl = (const uint4*)g_w1lo + (size_t)(n0 + lrow) * 128 + half_ * 2;
    const uint32_t dstoff = (uint32_t)(lrow * TPAD + half_ * 32);

    const int lane = tid & 31, wid = tid >> 5;
    const int wm = wid & 1, wn = wid >> 1;
    const uint32_t a_off = (uint32_t)((wm * 64 + (lane & 15)) * TPAD + (lane >> 4) * 16);
    const uint32_t b_off = (uint32_t)((wn * 32 + (lane & 7) + ((lane >> 4) << 3)) * TPAD +
                                      ((lane >> 3) & 1) * 16);

    float acc[4][4][4];
#pragma unroll
    for (int i = 0; i < 4; ++i)
#pragma unroll
        for (int j = 0; j < 4; ++j)
#pragma unroll
            for (int c = 0; c < 4; ++c) acc[i][j][c] = 0.0f;

    {
        const uint32_t base = sb;
#pragma unroll
        for (int c = 0; c < 2; ++c) {
            cp16(base + 0 * TILE_B + dstoff + c * 16, srcAh + c);
            cp16(base + 1 * TILE_B + dstoff + c * 16, srcAl + c);
            cp16(base + 2 * TILE_B + dstoff + c * 16, srcBh + c);
            cp16(base + 3 * TILE_B + dstoff + c * 16, srcBl + c);
        }
        cp_commit();
    }

    for (int kb = 0; kb < 32; ++kb) {
        const int cur = kb & 1;
        if (kb + 1 < 32) {
            const uint32_t base = sb + (1 - cur) * GATE_STAGE;
            const int co = (kb + 1) * 4;
#pragma unroll
            for (int c = 0; c < 2; ++c) {
                cp16(base + 0 * TILE_B + dstoff + c * 16, srcAh + co + c);
                cp16(base + 1 * TILE_B + dstoff + c * 16, srcAl + co + c);
                cp16(base + 2 * TILE_B + dstoff + c * 16, srcBh + co + c);
                cp16(base + 3 * TILE_B + dstoff + c * 16, srcBl + co + c);
            }
            cp_commit();
            cp_wait1();
        } else {
            cp_wait0();
        }
        __syncthreads();

        const uint32_t sAh = sb + cur * GATE_STAGE;
        const uint32_t sAl = sAh + TILE_B;
        const uint32_t sBh = sAh + 2 * TILE_B;
        const uint32_t sBl = sAh + 3 * TILE_B;
#pragma unroll
        for (int k16 = 0; k16 < 2; ++k16) {
            const uint32_t kadd = k16 * 32;
            uint32_t ah[4][4], al[4][4], bh[2][4], bl[2][4];
#pragma unroll
            for (int mt = 0; mt < 4; ++mt) {
                ldm4(ah[mt], sAh + a_off + mt * (16 * TPAD) + kadd);
                ldm4(al[mt], sAl + a_off + mt * (16 * TPAD) + kadd);
            }
#pragma unroll
            for (int g = 0; g < 2; ++g) {
                ldm4(bh[g], sBh + b_off + g * (16 * TPAD) + kadd);
                ldm4(bl[g], sBl + b_off + g * (16 * TPAD) + kadd);
            }
#pragma unroll
            for (int mt = 0; mt < 4; ++mt)
#pragma unroll
                for (int nt = 0; nt < 4; ++nt) {
                    const uint32_t* ph = &bh[nt >> 1][(nt & 1) * 2];
                    const uint32_t* pl = &bl[nt >> 1][(nt & 1) * 2];
                    mma16816(acc[mt][nt], ah[mt], ph);
                    mma16816(acc[mt][nt], al[mt], ph);
                    mma16816(acc[mt][nt], ah[mt], pl);
                }
        }
        __syncthreads();
    }

    // epilogue: bias + exact GELU -> g_gate (fp32)
#pragma unroll
    for (int mt = 0; mt < 4; ++mt) {
        const int rbase = m0 + wm * 64 + mt * 16 + (lane >> 2);
#pragma unroll
        for (int h = 0; h < 2; ++h) {
            const int gr = rbase + h * 8;
            float* gp = g_gate + (size_t)gr * DH + n0;
#pragma unroll
            for (int nt = 0; nt < 4; ++nt) {
                const int col = wn * 32 + nt * 8 + (lane & 3) * 2;
                float2 v;
                v.x = gelu_exact(acc[mt][nt][h * 2 + 0] + b1[n0 + col]);
                v.y = gelu_exact(acc[mt][nt][h * 2 + 1] + b1[n0 + col + 1]);
                *(float2*)(gp + col) = v;
            }
        }
    }
}

// ======================= routing (fp32 exact) =======================
__global__ __launch_bounds__(256) void routing_kernel(const float* __restrict__ W2,
                                                      const float* __restrict__ b2) {
    __shared__ float sW[NE * DH];
    const int tid = threadIdx.x;
    for (int idx = tid; idx < NE * DH; idx += 256) {
        int k = idx >> 3, j = idx & 7;
        sW[j * DH + k] = W2[idx];
    }
    __syncthreads();

    const int warp = tid >> 5, lane = tid & 31;
    const int b = blockIdx.x * 8 + warp;
    const float* gr = g_gate + (size_t)b * DH;

    float acc[NE];
#pragma unroll
    for (int j = 0; j < NE; ++j) acc[j] = 0.0f;
    for (int k = lane; k < DH; k += 32) {
        float gv = gr[k];
#pragma unroll
        for (int j = 0; j < NE; ++j) acc[j] += gv * sW[j * DH + k];
    }
#pragma unroll
    for (int off = 16; off; off >>= 1)
#pragma unroll
        for (int j = 0; j < NE; ++j)
            acc[j] += __shfl_down_sync(0xffffffffu, acc[j], off);

    if (lane == 0) {
        float s[NE];
#pragma unroll
        for (int j = 0; j < NE; ++j) s[j] = acc[j] + b2[j];
        int i0 = 0; float s0v = s[0];
#pragma unroll
        for (int j = 1; j < NE; ++j) if (s[j] > s0v) { s0v = s[j]; i0 = j; }
        int i1 = -1; float s1v = -3.4e38f;
#pragma unroll
        for (int j = 0; j < NE; ++j) if (j != i0 && s[j] > s1v) { s1v = s[j]; i1 = j; }
        float ed = expf(s1v - s0v);
        float denom = 1.0f + ed;
        float w0 = 1.0f / denom, w1 = ed / denom;

        int p0 = atomicAdd(&g_cnt[i0], 1);
        int p1 = atomicAdd(&g_cnt[i1], 1);
        g_tok[i0 * B_TOK + p0] = b;
        g_tok[i1 * B_TOK + p1] = b;
        g_slot[2 * b]     = i0 * B_TOK + p0;
        g_slot[2 * b + 1] = i1 * B_TOK + p1;
        g_wgt[2 * b]      = w0;
        g_wgt[2 * b + 1]  = w1;
    }
}

// ======================= expert GEMM: single-term Ah*Bh, tile 256x128, K-chunk 32 ==========
// R9-proven geometry (TPAD 80, 2x16B cp.async per row, warp 64x32), scaled to M=256.
// 512 threads, 16 warps (4m x 4n). Stage = Ah(256x80) | Bh(128x80). Double-buffered.
#define EA_TILE   20480          // 256*80
#define EB_TILE   10240          // 128*80
#define EXP_STAGE 30720
#define EXP_SMEM  61440

__global__ __launch_bounds__(512, 1) void expert_mma_kernel(const float* __restrict__ be) {
    extern __shared__ char smem[];
    __shared__ int ts[256];
    const int e   = blockIdx.z;
    const int cnt = g_cnt[e];
    const int m0  = blockIdx.y * 256;
    if (m0 >= cnt) return;
    const int n0  = blockIdx.x * 128;
    const int tid = threadIdx.x;
    const uint32_t sb = smem_u32(smem);

    if (tid < 256) {
        int r = m0 + tid;
        ts[tid] = (r < cnt) ? g_tok[e * B_TOK + r] : g_tok[e * B_TOK];
    }
    __syncthreads();

    // A: 512 threads cover 256 rows x 2 halves; B: threads <256 cover 128 rows x 2 halves
    const int lrow = tid >> 1, half_ = tid & 1;
    const int mytok = ts[lrow];
    const uint4* srcA = g_xhi + (size_t)mytok * 128 + half_ * 2;
    const uint32_t Adst = (uint32_t)(lrow * TPAD + half_ * 32);
    const uint4* srcB = (const uint4*)g_wehi + (size_t)(e * DOUT + n0 + lrow) * 128 + half_ * 2;
    const uint32_t Bdst = (uint32_t)(lrow * TPAD + half_ * 32);
    const bool doB = (tid < 256);

    const int lane = tid & 31, wid = tid >> 5;
    const int wm = wid & 3, wn = wid >> 2;
    const uint32_t a_off = (uint32_t)((wm * 64 + (lane & 15)) * TPAD + (lane >> 4) * 16);
    const uint32_t b_off = (uint32_t)((wn * 32 + (lane & 7) + ((lane >> 4) << 3)) * TPAD +
                                      ((lane >> 3) & 1) * 16);

    float acc[4][4][4];
#pragma unroll
    for (int i = 0; i < 4; ++i)
#pragma unroll
        for (int j = 0; j < 4; ++j)
#pragma unroll
            for (int c = 0; c < 4; ++c) acc[i][j][c] = 0.0f;

    {
        const uint32_t base = sb;
#pragma unroll
        for (int c = 0; c < 2; ++c) {
            cp16(base + Adst + c * 16, srcA + c);
            if (doB) cp16(base + EA_TILE + Bdst + c * 16, srcB + c);
        }
        cp_commit();
    }

    for (int kb = 0; kb < 32; ++kb) {
        const int cur = kb & 1;
        if (kb + 1 < 32) {
            const uint32_t base = sb + (1 - cur) * EXP_STAGE;
            const int co = (kb + 1) * 4;
#pragma unroll
            for (int c = 0; c < 2; ++c) {
                cp16(base + Adst + c * 16, srcA + co + c);
                if (doB) cp16(base + EA_TILE + Bdst + c * 16, srcB + co + c);
            }
            cp_commit();
            cp_wait1();
        } else {
            cp_wait0();
        }
        __syncthreads();

        const uint32_t sA = sb + cur * EXP_STAGE;
        const uint32_t sB = sA + EA_TILE;
#pragma unroll
        for (int k16 = 0; k16 < 2; ++k16) {
            const uint32_t kadd = k16 * 32;
            uint32_t ah[4][4], bh[2][4];
#pragma unroll
            for (int mt = 0; mt < 4; ++mt)
                ldm4(ah[mt], sA + a_off + mt * (16 * TPAD) + kadd);
#pragma unroll
            for (int g = 0; g < 2; ++g)
                ldm4(bh[g], sB + b_off + g * (16 * TPAD) + kadd);
#pragma unroll
            for (int mt = 0; mt < 4; ++mt)
#pragma unroll
                for (int nt = 0; nt < 4; ++nt) {
                    const uint32_t* ph = &bh[nt >> 1][(nt & 1) * 2];
                    mma16816(acc[mt][nt], ah[mt], ph);
                }
        }
        __syncthreads();
    }

    // epilogue: bias + predicated store
    const float* bb = be + e * DOUT + n0;
#pragma unroll
    for (int mt = 0; mt < 4; ++mt) {
        const int rbase = wm * 64 + mt * 16 + (lane >> 2);
#pragma unroll
        for (int h = 0; h < 2; ++h) {
            const int gr = m0 + rbase + h * 8;
            if (gr < cnt) {
                float* hp = g_hpre + ((size_t)e * B_TOK + gr) * DOUT + n0;
#pragma unroll
                for (int nt = 0; nt < 4; ++nt) {
                    const int col = wn * 32 + nt * 8 + (lane & 3) * 2;
                    float2 v;
                    v.x = acc[mt][nt][h * 2 + 0] + bb[col];
                    v.y = acc[mt][nt][h * 2 + 1] + bb[col + 1];
                    *(float2*)(hp + col) = v;
                }
            }
        }
    }
}

// ======================= LN + GELU + weighted combine =======================
__global__ __launch_bounds__(256) void combine_kernel(const float* __restrict__ ln_g,
                                                      const float* __restrict__ ln_b,
                                                      float* __restrict__ out) {
    const int b = blockIdx.x, tid = threadIdx.x;
    const int s0 = g_slot[2 * b], s1 = g_slot[2 * b + 1];
    const float w0 = g_wgt[2 * b], w1 = g_wgt[2 * b + 1];
    const int e0 = s0 >> 13, e1 = s1 >> 13;
    const float* r0 = g_hpre + (size_t)s0 * DOUT;
    const float* r1 = g_hpre + (size_t)s1 * DOUT;

    float v0[4], v1[4];
    float sum0 = 0.f, sq0 = 0.f, sum1 = 0.f, sq1 = 0.f;
#pragma unroll
    for (int i = 0; i < 4; ++i) {
        const int o = tid + i * 256;
        v0[i] = r0[o]; v1[i] = r1[o];
        sum0 += v0[i]; sq0 += v0[i] * v0[i];
        sum1 += v1[i]; sq1 += v1[i] * v1[i];
    }
    const int lane = tid & 31, wid = tid >> 5;
#pragma unroll
    for (int off = 16; off; off >>= 1) {
        sum0 += __shfl_down_sync(0xffffffffu, sum0, off);
        sq0  += __shfl_down_sync(0xffffffffu, sq0,  off);
        sum1 += __shfl_down_sync(0xffffffffu, sum1, off);
        sq1  += __shfl_down_sync(0xffffffffu, sq1,  off);
    }
    __shared__ float red[8][4];
    __shared__ float stats[4];
    if (lane == 0) { red[wid][0] = sum0; red[wid][1] = sq0; red[wid][2] = sum1; red[wid][3] = sq1; }
    __syncthreads();
    if (tid == 0) {
        float S0 = 0, Q0 = 0, S1 = 0, Q1 = 0;
#pragma unroll
        for (int w = 0; w < 8; ++w) { S0 += red[w][0]; Q0 += red[w][1]; S1 += red[w][2]; Q1 += red[w][3]; }
        const float inv = 1.0f / (float)DOUT;
        float mu0 = S0 * inv, mu1 = S1 * inv;
        float var0 = Q0 * inv - mu0 * mu0;
        float var1 = Q1 * inv - mu1 * mu1;
        stats[0] = mu0; stats[1] = rsqrtf(var0 + 1e-5f);
        stats[2] = mu1; stats[3] = rsqrtf(var1 + 1e-5f);
    }
    __syncthreads();
    const float mu0 = stats[0], rs0 = stats[1], mu1 = stats[2], rs1 = stats[3];
#pragma unroll
    for (int i = 0; i < 4; ++i) {
        const int o = tid + i * 256;
        const float h0 = (v0[i] - mu0) * rs0 * ln_g[e0 * DOUT + o] + ln_b[e0 * DOUT + o];
        const float h1 = (v1[i] - mu1) * rs1 * ln_g[e1 * DOUT + o] + ln_b[e1 * DOUT + o];
        out[(size_t)b * DOUT + o] = w0 * gelu_exact(h0) + w1 * gelu_exact(h1);
    }
}

// ======================= launch =======================
extern "C" void kernel_launch(void* const* d_in, const int* in_sizes, int n_in,
                              void* d_out, int out_size) {
    const float* x    = (const float*)d_in[0];
    const float* W1   = (const float*)d_in[1];
    const float* b1   = (const float*)d_in[2];
    const float* W2   = (const float*)d_in[3];
    const float* b2   = (const float*)d_in[4];
    const float* We   = (const float*)d_in[5];
    const float* be   = (const float*)d_in[6];
    const float* ln_g = (const float*)d_in[7];
    const float* ln_b = (const float*)d_in[8];
    float* out = (float*)d_out;

    cudaFuncSetAttribute(gate1_mma_kernel,  cudaFuncAttributeMaxDynamicSharedMemorySize, GATE_SMEM);
    cudaFuncSetAttribute(expert_mma_kernel, cudaFuncAttributeMaxDynamicSharedMemorySize, EXP_SMEM);

    convert_x_kernel<<<(B_TOK * DIN) / (256 * 4), 256>>>(x);
    convert_w1_kernel<<<dim3(DH / 32, DIN / 32), 256>>>(W1);
    convert_we_kernel<<<dim3(DOUT / 32, DIN / 32, NE), 256>>>(We);
    gate1_mma_kernel<<<dim3(DH / 128, B_TOK / 128), 256, GATE_SMEM>>>(b1);
    routing_kernel<<<B_TOK / 8, 256>>>(W2, b2);
    // m-grid worst case: one expert owns all 8192 tokens -> 32 m-tiles of 256
    expert_mma_kernel<<<dim3(DOUT / 128, B_TOK / 256, NE), 512, EXP_SMEM>>>(be);
    combine_kernel<<<B_TOK, 256>>>(ln_g, ln_b, out);
}